// round 12
// baseline (speedup 1.0000x reference)
#include <cuda_runtime.h>
#include <cuda_bf16.h>
#include <math.h>
#include <stdint.h>

#define BB 4
#define TT 90
#define FR (BB*TT)          // 360 frames
#define HW 224
#define DIN 256

// ---- scratch (device globals; no allocation) ----
__device__ __align__(16) uint4 g_wBv[32*4*32];     // B frags: [kt2][j][lane], 64KB
__device__ float g_biasf[64];
__device__ float g_pooled[FR*576];
__device__ float g_xm[FR*DIN];
__device__ float g_res[FR*DIN];
__device__ float g_u[FR*DIN];
__device__ float g_delta[FR*DIN];
__device__ __align__(16) float g_BC[FR*32];
__device__ float g_y[FR*DIN];

__device__ __forceinline__ uint32_t smem_u32(const void* p) {
    uint32_t a;
    asm("{ .reg .u64 t; cvta.to.shared.u64 t, %1; cvt.u32.u64 %0, t; }" : "=r"(a) : "l"(p));
    return a;
}
__device__ __forceinline__ void cp16(uint32_t dst, const void* src) {
    asm volatile("cp.async.cg.shared.global [%0], [%1], 16;" :: "r"(dst), "l"(src) : "memory");
}
#define CP_COMMIT() asm volatile("cp.async.commit_group;" ::: "memory")

// ================= one-time weight prep =================
__global__ void wfold_kernel(const float* __restrict__ conv_w,
                             const float* __restrict__ conv_b,
                             const float* __restrict__ gma,
                             const float* __restrict__ bta,
                             const float* __restrict__ mean,
                             const float* __restrict__ var)
{
    int idx = blockIdx.x * 256 + threadIdx.x;
    if (idx < 64) {
        float inv = gma[idx] * rsqrtf(var[idx] + 1e-5f);
        g_biasf[idx] = (conv_b[idx] - mean[idx]) * inv + bta[idx];
    }
    if (idx >= 32*4*32) return;
    int kt2  = idx >> 7;
    int j    = (idx >> 5) & 3;
    int lane = idx & 31;
    uint32_t comp[4];
    #pragma unroll
    for (int c = 0; c < 4; c++) {
        int nt = 2*j + (c >> 1); int h = c & 1;
        int n = nt*8 + (lane >> 2);
        int kbase = kt2*16 + h*8 + (lane & 3)*2;
        float inv = gma[n] * rsqrtf(var[n] + 1e-5f);
        float v[2];
        #pragma unroll
        for (int e = 0; e < 2; e++) {
            int k = kbase + e;
            int s = k >> 3, kx = k & 7;
            float val = 0.f;
            if (s < 63 && kx < 7) {
                int p = s / 7, ky = s % 7;
                int kt = p / 3, cc = p % 3;
                val = conv_w[(n*3 + cc)*147 + kt*49 + ky*7 + kx] * inv;
            }
            v[e] = val;
        }
        __nv_bfloat162 pk = __floats2bfloat162_rn(v[0], v[1]);
        comp[c] = *(uint32_t*)&pk;
    }
    g_wBv[idx] = make_uint4(comp[0], comp[1], comp[2], comp[3]);
}

__global__ void zero_pooled_kernel(int off) {
    int i = off + blockIdx.x * 256 + threadIdx.x;
    if (i < FR*576) g_pooled[i] = 0.f;
}

// ================= conv via mma.sync (HMMA) + cp.async B ring =================
// CTA = (frame, row-pair yp): D[M=128][N=64], M = y*64 + x (x<56 valid).
// 256 threads / 8 warps. Warp w = (m-pair w&3, n-half w>>2).
// A from smem patch (LDS.32); B prefetched gmem->smem ring (cp.async.cg),
// consumed as 2 LDS.128 per warp-kstep. Ring: 4 bufs x 2KB, 1 barrier/kstep.
#define SIN_U32ROW 116
#define SMEM_POOL_OFF 45936
#define SMEM_BSTAGE   48240
#define CONV_SMEM (SMEM_BSTAGE + 4*2048)    // 56,432 B -> 4 CTAs/SM

__device__ __forceinline__ void mma16816(float* c, const uint32_t* a,
                                         uint32_t b0, uint32_t b1) {
    asm volatile(
        "mma.sync.aligned.m16n8k16.row.col.f32.bf16.bf16.f32 "
        "{%0,%1,%2,%3}, {%4,%5,%6,%7}, {%8,%9}, {%0,%1,%2,%3};"
        : "+f"(c[0]), "+f"(c[1]), "+f"(c[2]), "+f"(c[3])
        : "r"(a[0]), "r"(a[1]), "r"(a[2]), "r"(a[3]), "r"(b0), "r"(b1));
}

__global__ __launch_bounds__(256, 4)
void conv_mma_kernel(const float* __restrict__ rgb)
{
    extern __shared__ char sm[];
    const uint32_t* in32 = (const uint32_t*)sm;
    float* s_pool        = (float*)(sm + SMEM_POOL_OFF);

    int blk = blockIdx.x;
    int yp = blk % 28; int frame = blk / 28;
    int t = frame % TT; int b = frame / TT;
    int tid = threadIdx.x;
    int w = tid >> 5; int lane = tid & 31;
    int g = lane >> 2; int q = lane & 3;
    int wm = w & 3;    int nh = w >> 2;

    const uint32_t sb = smem_u32(sm) + SMEM_BSTAGE;

    // prefetch B chunks for ksteps 0 and 1 (independent of patch load)
    if (tid < 128) cp16(sb + (uint32_t)tid*16u, (const char*)g_wBv + tid*16);
    CP_COMMIT();
    if (tid < 128) cp16(sb + 2048u + (uint32_t)tid*16u,
                        (const char*)g_wBv + 2048 + tid*16);
    CP_COMMIT();

    for (int i = tid; i < 576; i += 256) s_pool[i] = 0.f;

    // ---- input patch: 9 planes x 11 rows, 114 u32 (228 bf16) per row ----
    int rowbase = 8*yp - 3;
    for (int r = w; r < 99; r += 8) {
        int pIdx = r / 11, iy = r % 11;
        int tin = t + pIdx/3 - 1; int c = pIdx % 3;
        int grow = rowbase + iy;
        bool rv = (tin >= 0) && (tin < TT) && (grow >= 0) && (grow < HW);
        const float* src = rgb + (((size_t)(b*TT + tin)*3 + c)*HW + grow)*HW;
        uint32_t* dst = (uint32_t*)sm + (pIdx*11 + iy)*SIN_U32ROW;
        #pragma unroll
        for (int it = 0; it < 4; it++) {
            int x2 = lane + it*32;
            if (x2 < 114) {
                int c0 = 2*x2 - 3, c1 = c0 + 1;
                float v0 = (rv && c0 >= 0 && c0 < HW) ? src[c0] : 0.f;
                float v1 = (rv && c1 >= 0 && c1 < HW) ? src[c1] : 0.f;
                __nv_bfloat162 pk = __floats2bfloat162_rn(v0, v1);
                dst[x2] = *(uint32_t*)&pk;
            }
        }
    }
    __syncthreads();

    // per-thread A addressing (validated fragment mapping, R6)
    int x_lo = wm*16 + g;
    int x_hi = x_lo + 8; if (x_hi > 55) x_hi = 55;
    int blo = 2*x_lo + q;
    int bhi = 2*x_hi + q;

    float acc[2][4][4];
    #pragma unroll
    for (int y = 0; y < 2; y++)
        #pragma unroll
        for (int nt = 0; nt < 4; nt++)
            #pragma unroll
            for (int e = 0; e < 4; e++) acc[y][nt][e] = 0.f;

    #pragma unroll
    for (int kt2 = 0; kt2 < 32; kt2++) {
        const int s0 = 2*kt2, s1 = s0 + 1;
        const int p0 = s0 / 7, ky0 = s0 - 7*p0;
        const int p1 = s1 / 7, ky1 = s1 - 7*p1;
        const int o0 = (p0*11 + ky0)*SIN_U32ROW;
        // s1==63 is the zero-weight pad slot: clamp to a VALID smem row
        const int o1 = (s1 == 63) ? o0 : (p1*11 + ky1)*SIN_U32ROW;

        // ring: ensure chunk kt2 landed (in-order retirement; 1 younger OK)
        if (kt2 == 31) asm volatile("cp.async.wait_group 0;" ::: "memory");
        else           asm volatile("cp.async.wait_group 1;" ::: "memory");
        __syncthreads();   // publish staged chunk; frees buf consumed 2 steps ago

        // prefetch chunk kt2+2 into buf (kt2+2)&3 (consumed at kt2-2: free)
        if (kt2 + 2 < 32) {
            if (tid < 128)
                cp16(sb + (uint32_t)(((kt2 + 2) & 3)*2048 + tid*16),
                     (const char*)g_wBv + (kt2 + 2)*2048 + tid*16);
            CP_COMMIT();
        }

        const uint4* sB = (const uint4*)(sm + SMEM_BSTAGE + (kt2 & 3)*2048);
        uint4 B0 = sB[nh*64 + lane];
        uint4 B1 = sB[nh*64 + 32 + lane];

        uint32_t a0[4], a1[4];
        a0[0] = in32[o0 + blo];        a0[1] = in32[o0 + bhi];
        a0[2] = in32[o1 + blo];        a0[3] = in32[o1 + bhi];
        a1[0] = in32[o0 + 464 + blo];  a1[1] = in32[o0 + 464 + bhi];
        a1[2] = in32[o1 + 464 + blo];  a1[3] = in32[o1 + 464 + bhi];

        mma16816(acc[0][0], a0, B0.x, B0.y);  mma16816(acc[1][0], a1, B0.x, B0.y);
        mma16816(acc[0][1], a0, B0.z, B0.w);  mma16816(acc[1][1], a1, B0.z, B0.w);
        mma16816(acc[0][2], a0, B1.x, B1.y);  mma16816(acc[1][2], a1, B1.x, B1.y);
        mma16816(acc[0][3], a0, B1.z, B1.w);  mma16816(acc[1][3], a1, B1.z, B1.w);
    }

    // ---- epilogue: bias + exact GELU + pool bins (floor 18/19/19) ----
    const float i18 = 1.f/18.f, i19 = 1.f/19.f;
    #pragma unroll
    for (int y = 0; y < 2; y++) {
        int rowg = 2*yp + y;
        float rw = (rowg < 18) ? i18 : i19;
        int roff = (rowg < 18) ? 0 : ((rowg < 37) ? 3 : 6);
        #pragma unroll
        for (int h = 0; h < 2; h++) {
            int x = wm*16 + g + h*8;
            if (x < 56) {
                int xbin = (x < 18) ? 0 : ((x < 37) ? 1 : 2);
                float cw = ((x < 18) ? i18 : i19) * rw;
                #pragma unroll
                for (int nt = 0; nt < 4; nt++) {
                    int ch0 = (nh*4 + nt)*8 + q*2;
                    float v0 = acc[y][nt][h*2]     + __ldg(g_biasf + ch0);
                    float v1 = acc[y][nt][h*2 + 1] + __ldg(g_biasf + ch0 + 1);
                    float g0 = 0.5f*v0*(1.0f + erff(v0*0.70710678118654752f));
                    float g1 = 0.5f*v1*(1.0f + erff(v1*0.70710678118654752f));
                    atomicAdd(&s_pool[ch0*9 + roff + xbin],       g0*cw);
                    atomicAdd(&s_pool[(ch0 + 1)*9 + roff + xbin], g1*cw);
                }
            }
        }
    }
    __syncthreads();
    int base = frame*576;
    for (int i = tid; i < 576; i += 256) atomicAdd(&g_pooled[base + i], s_pool[i]);
}

// ================= Mamba chain — coalesced warp-per-row GEMVs =================
__global__ void proj_inproj_kernel(const float* __restrict__ proj_w,
                                   const float* __restrict__ proj_b,
                                   const float* __restrict__ in_w)
{
    __shared__ float s_p[576];
    __shared__ float s_x[128];
    int pos = blockIdx.x;
    int tid = threadIdx.x;           // 256
    int w = tid >> 5, lane = tid & 31;
    for (int i = tid; i < 576; i += 256) s_p[i] = g_pooled[pos*576 + i];
    __syncthreads();

    #pragma unroll
    for (int rr = 0; rr < 16; rr++) {
        int row = w*16 + rr;
        const float* wr = proj_w + row*576;
        float a = 0.f;
        #pragma unroll
        for (int k = lane; k < 576; k += 32) a = fmaf(__ldg(wr + k), s_p[k], a);
        #pragma unroll
        for (int o = 16; o > 0; o >>= 1) a += __shfl_xor_sync(0xffffffffu, a, o);
        if (lane == 0) s_x[row] = a + __ldg(proj_b + row);
    }
    __syncthreads();

    #pragma unroll
    for (int rr = 0; rr < 64; rr++) {
        int row = w*64 + rr;
        const float* wr = in_w + row*128;
        float a = 0.f;
        #pragma unroll
        for (int k = lane; k < 128; k += 32) a = fmaf(__ldg(wr + k), s_x[k], a);
        #pragma unroll
        for (int o = 16; o > 0; o >>= 1) a += __shfl_xor_sync(0xffffffffu, a, o);
        if (lane == 0) {
            if (row < 256) g_xm[pos*256 + row] = a;
            else           g_res[pos*256 + (row - 256)] = a;
        }
    }
}

__global__ void conv1d_xproj_kernel(const float* __restrict__ cw,
                                    const float* __restrict__ cb,
                                    const float* __restrict__ xw,
                                    const float* __restrict__ dtw,
                                    const float* __restrict__ dtb)
{
    __shared__ float s_u[256];
    __shared__ float s_xd[40];
    int pos = blockIdx.x; int b = pos / TT; int l = pos % TT;
    int d = threadIdx.x;             // 256
    int w = d >> 5, lane = d & 31;

    float xc = cb[d];
    #pragma unroll
    for (int k = 0; k < 4; k++) {
        int li = l - 3 + k;
        if (li >= 0) xc = fmaf(g_xm[(b*TT + li)*256 + d], cw[d*4 + k], xc);
    }
    float u = xc / (1.f + expf(-xc));
    s_u[d] = u;
    g_u[pos*256 + d] = u;
    __syncthreads();

    #pragma unroll
    for (int rr = 0; rr < 5; rr++) {
        int row = w*5 + rr;
        const float* wr = xw + row*256;
        float a = 0.f;
        #pragma unroll
        for (int k = lane; k < 256; k += 32) a = fmaf(__ldg(wr + k), s_u[k], a);
        #pragma unroll
        for (int o = 16; o > 0; o >>= 1) a += __shfl_xor_sync(0xffffffffu, a, o);
        if (lane == 0) s_xd[row] = a;
    }
    __syncthreads();

    float dr = dtb[d];
    #pragma unroll
    for (int k = 0; k < 8; k++) dr = fmaf(dtw[d*8 + k], s_xd[k], dr);
    float delta = (dr > 20.f) ? dr : log1pf(expf(dr));
    g_delta[pos*256 + d] = delta;
    if (d < 32) g_BC[pos*32 + d] = s_xd[8 + d];
}

__global__ void scan_kernel(const float* __restrict__ A_log,
                            const float* __restrict__ Dp)
{
    int b = blockIdx.x >> 3;
    int d = ((blockIdx.x & 7) << 5) + threadIdx.x;
    float A[16], h[16];
    #pragma unroll
    for (int n = 0; n < 16; n++) { A[n] = -expf(A_log[d*16 + n]); h[n] = 0.f; }
    float Dd = Dp[d];

    for (int l = 0; l < TT; l++) {
        int pos = b*TT + l;
        float delta = g_delta[pos*256 + d];
        float u     = g_u[pos*256 + d];
        float res   = g_res[pos*256 + d];
        const float4* BC4 = (const float4*)(g_BC + pos*32);
        float4 Bv[4], Cv[4];
        #pragma unroll
        for (int i = 0; i < 4; i++) Bv[i] = __ldg(BC4 + i);
        #pragma unroll
        for (int i = 0; i < 4; i++) Cv[i] = __ldg(BC4 + 4 + i);
        float du = delta * u;
        float y = 0.f;
        const float* Bf = (const float*)Bv;
        const float* Cf = (const float*)Cv;
        #pragma unroll
        for (int n = 0; n < 16; n++) {
            float dA = expf(delta * A[n]);
            h[n] = fmaf(dA, h[n], du * Bf[n]);
            y = fmaf(h[n], Cf[n], y);
        }
        y = fmaf(u, Dd, y);
        y *= res / (1.f + expf(-res));
        g_y[pos*256 + d] = y;
    }
}

__global__ void outproj_kernel(const float* __restrict__ ow,
                               float* __restrict__ out)
{
    __shared__ float s_y[256];
    int pos = blockIdx.x;
    int tid = threadIdx.x;           // 256
    int w = tid >> 5, lane = tid & 31;
    s_y[tid] = g_y[pos*256 + tid];
    __syncthreads();
    #pragma unroll
    for (int rr = 0; rr < 16; rr++) {
        int row = w*16 + rr;
        const float* wr = ow + row*256;
        float a = 0.f;
        #pragma unroll
        for (int k = lane; k < 256; k += 32) a = fmaf(__ldg(wr + k), s_y[k], a);
        #pragma unroll
        for (int o = 16; o > 0; o >>= 1) a += __shfl_xor_sync(0xffffffffu, a, o);
        if (lane == 0) out[pos*128 + row] = a;
    }
}

// ============================================================
extern "C" void kernel_launch(void* const* d_in, const int* in_sizes, int n_in,
                              void* d_out, int out_size)
{
    (void)in_sizes; (void)n_in; (void)out_size;
    const float* rgb     = (const float*)d_in[0];
    const float* conv_w  = (const float*)d_in[1];
    const float* conv_b  = (const float*)d_in[2];
    const float* bn_g    = (const float*)d_in[3];
    const float* bn_b    = (const float*)d_in[4];
    const float* bn_m    = (const float*)d_in[5];
    const float* bn_v    = (const float*)d_in[6];
    const float* proj_w  = (const float*)d_in[7];
    const float* proj_b  = (const float*)d_in[8];
    const float* m_in_w  = (const float*)d_in[9];
    const float* m_cw    = (const float*)d_in[10];
    const float* m_cb    = (const float*)d_in[11];
    const float* m_xw    = (const float*)d_in[12];
    const float* m_dtw   = (const float*)d_in[13];
    const float* m_dtb   = (const float*)d_in[14];
    const float* m_Alog  = (const float*)d_in[15];
    const float* m_D     = (const float*)d_in[16];
    const float* m_ow    = (const float*)d_in[17];
    float* out = (float*)d_out;

    cudaFuncSetAttribute(conv_mma_kernel,
                         cudaFuncAttributeMaxDynamicSharedMemorySize, CONV_SMEM);

    // wfold + 2 zeros position conv at ncu launch index 5
    wfold_kernel<<<(32*4*32 + 255)/256, 256>>>(conv_w, conv_b, bn_g, bn_b, bn_m, bn_v);
    const int H = (FR*576) / 2;
    zero_pooled_kernel<<<(H + 255)/256, 256>>>(0);
    zero_pooled_kernel<<<(H + 255)/256, 256>>>(H);

    conv_mma_kernel<<<FR*28, 256, CONV_SMEM>>>(rgb);

    proj_inproj_kernel<<<FR, 256>>>(proj_w, proj_b, m_in_w);
    conv1d_xproj_kernel<<<FR, 256>>>(m_cw, m_cb, m_xw, m_dtw, m_dtb);
    scan_kernel<<<32, 32>>>(m_Alog, m_D);
    outproj_kernel<<<FR, 256>>>(m_ow, out);
}

// round 13
// speedup vs baseline: 1.3791x; 1.3791x over previous
#include <cuda_runtime.h>
#include <cuda_bf16.h>
#include <math.h>
#include <stdint.h>

#define BB 4
#define TT 90
#define FR (BB*TT)          // 360 frames
#define HW 224
#define DIN 256

// ---- scratch (device globals; no allocation) ----
__device__ __align__(16) uint4 g_wBv[32*4*32];     // B frags: [kt2][j][lane], 64KB
__device__ float g_biasf[64];
__device__ float g_pooled[FR*576];
__device__ float g_xm[FR*DIN];
__device__ float g_res[FR*DIN];
__device__ float g_u[FR*DIN];
__device__ float g_delta[FR*DIN];
__device__ __align__(16) float g_BC[FR*32];
__device__ float g_y[FR*DIN];

// ================= one-time weight prep =================
__global__ void wfold_kernel(const float* __restrict__ conv_w,
                             const float* __restrict__ conv_b,
                             const float* __restrict__ gma,
                             const float* __restrict__ bta,
                             const float* __restrict__ mean,
                             const float* __restrict__ var)
{
    int idx = blockIdx.x * 256 + threadIdx.x;
    if (idx < 64) {
        float inv = gma[idx] * rsqrtf(var[idx] + 1e-5f);
        g_biasf[idx] = (conv_b[idx] - mean[idx]) * inv + bta[idx];
    }
    if (idx >= 32*4*32) return;
    int kt2  = idx >> 7;
    int j    = (idx >> 5) & 3;
    int lane = idx & 31;
    uint32_t comp[4];
    #pragma unroll
    for (int c = 0; c < 4; c++) {
        int nt = 2*j + (c >> 1); int h = c & 1;
        int n = nt*8 + (lane >> 2);
        int kbase = kt2*16 + h*8 + (lane & 3)*2;
        float inv = gma[n] * rsqrtf(var[n] + 1e-5f);
        float v[2];
        #pragma unroll
        for (int e = 0; e < 2; e++) {
            int k = kbase + e;
            int s = k >> 3, kx = k & 7;
            float val = 0.f;
            if (s < 63 && kx < 7) {
                int p = s / 7, ky = s % 7;
                int kt = p / 3, cc = p % 3;
                val = conv_w[(n*3 + cc)*147 + kt*49 + ky*7 + kx] * inv;
            }
            v[e] = val;
        }
        __nv_bfloat162 pk = __floats2bfloat162_rn(v[0], v[1]);
        comp[c] = *(uint32_t*)&pk;
    }
    g_wBv[idx] = make_uint4(comp[0], comp[1], comp[2], comp[3]);
}

__global__ void zero_pooled_kernel(int off) {
    int i = off + blockIdx.x * 256 + threadIdx.x;
    if (i < FR*576) g_pooled[i] = 0.f;
}

// ================= conv via mma.sync (HMMA) =================
// CTA = (frame, row-pair yp): D[M=128][N=64], M = y*64 + x (x<56 valid).
// 256 threads / 8 warps. Warp w = (m-pair w&3, n-half w>>2).
// 3 CTAs/SM (84-reg budget): B double-buffered in registers, B table
// L1-resident (83KB carveout >= 64KB table).
#define SIN_U32ROW 116
#define SMEM_POOL_OFF 45936
#define CONV_SMEM (SMEM_POOL_OFF + 576*4)   // 48,240 B

__device__ __forceinline__ void mma16816(float* c, const uint32_t* a,
                                         uint32_t b0, uint32_t b1) {
    asm volatile(
        "mma.sync.aligned.m16n8k16.row.col.f32.bf16.bf16.f32 "
        "{%0,%1,%2,%3}, {%4,%5,%6,%7}, {%8,%9}, {%0,%1,%2,%3};"
        : "+f"(c[0]), "+f"(c[1]), "+f"(c[2]), "+f"(c[3])
        : "r"(a[0]), "r"(a[1]), "r"(a[2]), "r"(a[3]), "r"(b0), "r"(b1));
}

__global__ __launch_bounds__(256, 3)
void conv_mma_kernel(const float* __restrict__ rgb)
{
    extern __shared__ char sm[];
    const uint32_t* in32 = (const uint32_t*)sm;
    float* s_pool        = (float*)(sm + SMEM_POOL_OFF);

    int blk = blockIdx.x;
    int yp = blk % 28; int frame = blk / 28;
    int t = frame % TT; int b = frame / TT;
    int tid = threadIdx.x;
    int w = tid >> 5; int lane = tid & 31;
    int g = lane >> 2; int q = lane & 3;
    int wm = w & 3;    int nh = w >> 2;

    for (int i = tid; i < 576; i += 256) s_pool[i] = 0.f;

    // ---- input patch: 9 planes x 11 rows, 114 u32 (228 bf16) per row ----
    int rowbase = 8*yp - 3;
    for (int r = w; r < 99; r += 8) {
        int pIdx = r / 11, iy = r % 11;
        int tin = t + pIdx/3 - 1; int c = pIdx % 3;
        int grow = rowbase + iy;
        bool rv = (tin >= 0) && (tin < TT) && (grow >= 0) && (grow < HW);
        const float* src = rgb + (((size_t)(b*TT + tin)*3 + c)*HW + grow)*HW;
        uint32_t* dst = (uint32_t*)sm + (pIdx*11 + iy)*SIN_U32ROW;
        #pragma unroll
        for (int it = 0; it < 4; it++) {
            int x2 = lane + it*32;
            if (x2 < 114) {
                int c0 = 2*x2 - 3, c1 = c0 + 1;
                float v0 = (rv && c0 >= 0 && c0 < HW) ? src[c0] : 0.f;
                float v1 = (rv && c1 >= 0 && c1 < HW) ? src[c1] : 0.f;
                __nv_bfloat162 pk = __floats2bfloat162_rn(v0, v1);
                dst[x2] = *(uint32_t*)&pk;
            }
        }
    }
    __syncthreads();

    // per-thread A addressing (validated fragment mapping, R6)
    int x_lo = wm*16 + g;
    int x_hi = x_lo + 8; if (x_hi > 55) x_hi = 55;
    int blo = 2*x_lo + q;
    int bhi = 2*x_hi + q;

    float acc[2][4][4];
    #pragma unroll
    for (int y = 0; y < 2; y++)
        #pragma unroll
        for (int nt = 0; nt < 4; nt++)
            #pragma unroll
            for (int e = 0; e < 4; e++) acc[y][nt][e] = 0.f;

    const uint4* btab = g_wBv + nh*64 + lane;

    // register double-buffer for B
    uint4 B0 = __ldg(btab);
    uint4 B1 = __ldg(btab + 32);

    #pragma unroll
    for (int kt2 = 0; kt2 < 32; kt2++) {
        const int s0 = 2*kt2, s1 = s0 + 1;
        const int p0 = s0 / 7, ky0 = s0 - 7*p0;
        const int p1 = s1 / 7, ky1 = s1 - 7*p1;
        const int o0 = (p0*11 + ky0)*SIN_U32ROW;
        // s1==63 is the zero-weight pad slot: clamp to a VALID smem row
        const int o1 = (s1 == 63) ? o0 : (p1*11 + ky1)*SIN_U32ROW;

        // prefetch next kstep's B into registers (hides LDG latency)
        uint4 nB0, nB1;
        if (kt2 < 31) {
            nB0 = __ldg(btab + (kt2 + 1)*128);
            nB1 = __ldg(btab + (kt2 + 1)*128 + 32);
        }

        uint32_t a0[4], a1[4];
        a0[0] = in32[o0 + blo];        a0[1] = in32[o0 + bhi];
        a0[2] = in32[o1 + blo];        a0[3] = in32[o1 + bhi];
        a1[0] = in32[o0 + 464 + blo];  a1[1] = in32[o0 + 464 + bhi];
        a1[2] = in32[o1 + 464 + blo];  a1[3] = in32[o1 + 464 + bhi];

        mma16816(acc[0][0], a0, B0.x, B0.y);  mma16816(acc[1][0], a1, B0.x, B0.y);
        mma16816(acc[0][1], a0, B0.z, B0.w);  mma16816(acc[1][1], a1, B0.z, B0.w);
        mma16816(acc[0][2], a0, B1.x, B1.y);  mma16816(acc[1][2], a1, B1.x, B1.y);
        mma16816(acc[0][3], a0, B1.z, B1.w);  mma16816(acc[1][3], a1, B1.z, B1.w);

        B0 = nB0; B1 = nB1;
    }

    // ---- epilogue: bias + exact GELU + pool bins (floor 18/19/19) ----
    const float i18 = 1.f/18.f, i19 = 1.f/19.f;
    #pragma unroll
    for (int y = 0; y < 2; y++) {
        int rowg = 2*yp + y;
        float rw = (rowg < 18) ? i18 : i19;
        int roff = (rowg < 18) ? 0 : ((rowg < 37) ? 3 : 6);
        #pragma unroll
        for (int h = 0; h < 2; h++) {
            int x = wm*16 + g + h*8;
            if (x < 56) {
                int xbin = (x < 18) ? 0 : ((x < 37) ? 1 : 2);
                float cw = ((x < 18) ? i18 : i19) * rw;
                #pragma unroll
                for (int nt = 0; nt < 4; nt++) {
                    int ch0 = (nh*4 + nt)*8 + q*2;
                    float v0 = acc[y][nt][h*2]     + __ldg(g_biasf + ch0);
                    float v1 = acc[y][nt][h*2 + 1] + __ldg(g_biasf + ch0 + 1);
                    float g0 = 0.5f*v0*(1.0f + erff(v0*0.70710678118654752f));
                    float g1 = 0.5f*v1*(1.0f + erff(v1*0.70710678118654752f));
                    atomicAdd(&s_pool[ch0*9 + roff + xbin],       g0*cw);
                    atomicAdd(&s_pool[(ch0 + 1)*9 + roff + xbin], g1*cw);
                }
            }
        }
    }
    __syncthreads();
    int base = frame*576;
    for (int i = tid; i < 576; i += 256) atomicAdd(&g_pooled[base + i], s_pool[i]);
}

// ================= Mamba chain — coalesced warp-per-row GEMVs =================
__global__ void proj_inproj_kernel(const float* __restrict__ proj_w,
                                   const float* __restrict__ proj_b,
                                   const float* __restrict__ in_w)
{
    __shared__ float s_p[576];
    __shared__ float s_x[128];
    int pos = blockIdx.x;
    int tid = threadIdx.x;           // 256
    int w = tid >> 5, lane = tid & 31;
    for (int i = tid; i < 576; i += 256) s_p[i] = g_pooled[pos*576 + i];
    __syncthreads();

    #pragma unroll
    for (int rr = 0; rr < 16; rr++) {
        int row = w*16 + rr;
        const float* wr = proj_w + row*576;
        float a = 0.f;
        #pragma unroll
        for (int k = lane; k < 576; k += 32) a = fmaf(__ldg(wr + k), s_p[k], a);
        #pragma unroll
        for (int o = 16; o > 0; o >>= 1) a += __shfl_xor_sync(0xffffffffu, a, o);
        if (lane == 0) s_x[row] = a + __ldg(proj_b + row);
    }
    __syncthreads();

    #pragma unroll
    for (int rr = 0; rr < 64; rr++) {
        int row = w*64 + rr;
        const float* wr = in_w + row*128;
        float a = 0.f;
        #pragma unroll
        for (int k = lane; k < 128; k += 32) a = fmaf(__ldg(wr + k), s_x[k], a);
        #pragma unroll
        for (int o = 16; o > 0; o >>= 1) a += __shfl_xor_sync(0xffffffffu, a, o);
        if (lane == 0) {
            if (row < 256) g_xm[pos*256 + row] = a;
            else           g_res[pos*256 + (row - 256)] = a;
        }
    }
}

__global__ void conv1d_xproj_kernel(const float* __restrict__ cw,
                                    const float* __restrict__ cb,
                                    const float* __restrict__ xw,
                                    const float* __restrict__ dtw,
                                    const float* __restrict__ dtb)
{
    __shared__ float s_u[256];
    __shared__ float s_xd[40];
    int pos = blockIdx.x; int b = pos / TT; int l = pos % TT;
    int d = threadIdx.x;             // 256
    int w = d >> 5, lane = d & 31;

    float xc = cb[d];
    #pragma unroll
    for (int k = 0; k < 4; k++) {
        int li = l - 3 + k;
        if (li >= 0) xc = fmaf(g_xm[(b*TT + li)*256 + d], cw[d*4 + k], xc);
    }
    float u = xc / (1.f + expf(-xc));
    s_u[d] = u;
    g_u[pos*256 + d] = u;
    __syncthreads();

    #pragma unroll
    for (int rr = 0; rr < 5; rr++) {
        int row = w*5 + rr;
        const float* wr = xw + row*256;
        float a = 0.f;
        #pragma unroll
        for (int k = lane; k < 256; k += 32) a = fmaf(__ldg(wr + k), s_u[k], a);
        #pragma unroll
        for (int o = 16; o > 0; o >>= 1) a += __shfl_xor_sync(0xffffffffu, a, o);
        if (lane == 0) s_xd[row] = a;
    }
    __syncthreads();

    float dr = dtb[d];
    #pragma unroll
    for (int k = 0; k < 8; k++) dr = fmaf(dtw[d*8 + k], s_xd[k], dr);
    float delta = (dr > 20.f) ? dr : log1pf(expf(dr));
    g_delta[pos*256 + d] = delta;
    if (d < 32) g_BC[pos*32 + d] = s_xd[8 + d];
}

__global__ void scan_kernel(const float* __restrict__ A_log,
                            const float* __restrict__ Dp)
{
    int b = blockIdx.x >> 3;
    int d = ((blockIdx.x & 7) << 5) + threadIdx.x;
    float A[16], h[16];
    #pragma unroll
    for (int n = 0; n < 16; n++) { A[n] = -expf(A_log[d*16 + n]); h[n] = 0.f; }
    float Dd = Dp[d];

    for (int l = 0; l < TT; l++) {
        int pos = b*TT + l;
        float delta = g_delta[pos*256 + d];
        float u     = g_u[pos*256 + d];
        float res   = g_res[pos*256 + d];
        const float4* BC4 = (const float4*)(g_BC + pos*32);
        float4 Bv[4], Cv[4];
        #pragma unroll
        for (int i = 0; i < 4; i++) Bv[i] = __ldg(BC4 + i);
        #pragma unroll
        for (int i = 0; i < 4; i++) Cv[i] = __ldg(BC4 + 4 + i);
        float du = delta * u;
        float y = 0.f;
        const float* Bf = (const float*)Bv;
        const float* Cf = (const float*)Cv;
        #pragma unroll
        for (int n = 0; n < 16; n++) {
            float dA = expf(delta * A[n]);
            h[n] = fmaf(dA, h[n], du * Bf[n]);
            y = fmaf(h[n], Cf[n], y);
        }
        y = fmaf(u, Dd, y);
        y *= res / (1.f + expf(-res));
        g_y[pos*256 + d] = y;
    }
}

__global__ void outproj_kernel(const float* __restrict__ ow,
                               float* __restrict__ out)
{
    __shared__ float s_y[256];
    int pos = blockIdx.x;
    int tid = threadIdx.x;           // 256
    int w = tid >> 5, lane = tid & 31;
    s_y[tid] = g_y[pos*256 + tid];
    __syncthreads();
    #pragma unroll
    for (int rr = 0; rr < 16; rr++) {
        int row = w*16 + rr;
        const float* wr = ow + row*256;
        float a = 0.f;
        #pragma unroll
        for (int k = lane; k < 256; k += 32) a = fmaf(__ldg(wr + k), s_y[k], a);
        #pragma unroll
        for (int o = 16; o > 0; o >>= 1) a += __shfl_xor_sync(0xffffffffu, a, o);
        if (lane == 0) out[pos*128 + row] = a;
    }
}

// ============================================================
extern "C" void kernel_launch(void* const* d_in, const int* in_sizes, int n_in,
                              void* d_out, int out_size)
{
    (void)in_sizes; (void)n_in; (void)out_size;
    const float* rgb     = (const float*)d_in[0];
    const float* conv_w  = (const float*)d_in[1];
    const float* conv_b  = (const float*)d_in[2];
    const float* bn_g    = (const float*)d_in[3];
    const float* bn_b    = (const float*)d_in[4];
    const float* bn_m    = (const float*)d_in[5];
    const float* bn_v    = (const float*)d_in[6];
    const float* proj_w  = (const float*)d_in[7];
    const float* proj_b  = (const float*)d_in[8];
    const float* m_in_w  = (const float*)d_in[9];
    const float* m_cw    = (const float*)d_in[10];
    const float* m_cb    = (const float*)d_in[11];
    const float* m_xw    = (const float*)d_in[12];
    const float* m_dtw   = (const float*)d_in[13];
    const float* m_dtb   = (const float*)d_in[14];
    const float* m_Alog  = (const float*)d_in[15];
    const float* m_D     = (const float*)d_in[16];
    const float* m_ow    = (const float*)d_in[17];
    float* out = (float*)d_out;

    cudaFuncSetAttribute(conv_mma_kernel,
                         cudaFuncAttributeMaxDynamicSharedMemorySize, CONV_SMEM);

    // wfold + 2 zeros position conv at ncu launch index 5
    wfold_kernel<<<(32*4*32 + 255)/256, 256>>>(conv_w, conv_b, bn_g, bn_b, bn_m, bn_v);
    const int H = (FR*576) / 2;
    zero_pooled_kernel<<<(H + 255)/256, 256>>>(0);
    zero_pooled_kernel<<<(H + 255)/256, 256>>>(H);

    conv_mma_kernel<<<FR*28, 256, CONV_SMEM>>>(rgb);

    proj_inproj_kernel<<<FR, 256>>>(proj_w, proj_b, m_in_w);
    conv1d_xproj_kernel<<<FR, 256>>>(m_cw, m_cb, m_xw, m_dtw, m_dtb);
    scan_kernel<<<32, 32>>>(m_Alog, m_D);
    outproj_kernel<<<FR, 256>>>(m_ow, out);
}

// round 14
// speedup vs baseline: 1.8695x; 1.3556x over previous
#include <cuda_runtime.h>
#include <cuda_bf16.h>
#include <math.h>
#include <stdint.h>

#define BB 4
#define TT 90
#define FR (BB*TT)          // 360 frames
#define HW 224
#define DIN 256

// ---- scratch (device globals; no allocation) ----
__device__ __align__(16) uint4 g_wBv[32*4*32];     // B frags: [kt2][j][lane], 64KB
__device__ float g_biasf[64];
__device__ float g_pooled[FR*576];
__device__ float g_xm[FR*DIN];
__device__ float g_res[FR*DIN];
__device__ float g_u[FR*DIN];
__device__ float g_delta[FR*DIN];
__device__ __align__(16) float g_BC[FR*32];
__device__ float g_y[FR*DIN];

// ================= one-time prep: BN-fold weights + zero pooled =================
__global__ void prep_kernel(const float* __restrict__ conv_w,
                            const float* __restrict__ conv_b,
                            const float* __restrict__ gma,
                            const float* __restrict__ bta,
                            const float* __restrict__ mean,
                            const float* __restrict__ var)
{
    int idx = blockIdx.x * 256 + threadIdx.x;
    // zero pooled accumulator (FR*576 = 207,360)
    if (idx < FR*576) g_pooled[idx] = 0.f;
    if (idx < 64) {
        float inv = gma[idx] * rsqrtf(var[idx] + 1e-5f);
        g_biasf[idx] = (conv_b[idx] - mean[idx]) * inv + bta[idx];
    }
    if (idx >= 32*4*32) return;
    int kt2  = idx >> 7;
    int j    = (idx >> 5) & 3;
    int lane = idx & 31;
    uint32_t comp[4];
    #pragma unroll
    for (int c = 0; c < 4; c++) {
        int nt = 2*j + (c >> 1); int h = c & 1;
        int n = nt*8 + (lane >> 2);
        int kbase = kt2*16 + h*8 + (lane & 3)*2;
        float inv = gma[n] * rsqrtf(var[n] + 1e-5f);
        float v[2];
        #pragma unroll
        for (int e = 0; e < 2; e++) {
            int k = kbase + e;
            int s = k >> 3, kx = k & 7;
            float val = 0.f;
            if (s < 63 && kx < 7) {
                int p = s / 7, ky = s % 7;
                int kt = p / 3, cc = p % 3;
                val = conv_w[(n*3 + cc)*147 + kt*49 + ky*7 + kx] * inv;
            }
            v[e] = val;
        }
        __nv_bfloat162 pk = __floats2bfloat162_rn(v[0], v[1]);
        comp[c] = *(uint32_t*)&pk;
    }
    g_wBv[idx] = make_uint4(comp[0], comp[1], comp[2], comp[3]);
}

// ================= conv via mma.sync (HMMA) — R10 core =================
// CTA = (frame, row-pair yp): D[M=128][N=64], M = y*64 + x (x<56 valid).
// 256 threads / 8 warps. Warp w = (m-pair w&3, n-half w>>2).
// A from smem patch (LDS.32), B from gmem frag table (LDG.128). 4 CTAs/SM.
#define SIN_U32ROW 116
#define SMEM_POOL_OFF 45936
#define CONV_SMEM (SMEM_POOL_OFF + 576*4)   // 48,240 B

__device__ __forceinline__ void mma16816(float* c, const uint32_t* a,
                                         uint32_t b0, uint32_t b1) {
    asm volatile(
        "mma.sync.aligned.m16n8k16.row.col.f32.bf16.bf16.f32 "
        "{%0,%1,%2,%3}, {%4,%5,%6,%7}, {%8,%9}, {%0,%1,%2,%3};"
        : "+f"(c[0]), "+f"(c[1]), "+f"(c[2]), "+f"(c[3])
        : "r"(a[0]), "r"(a[1]), "r"(a[2]), "r"(a[3]), "r"(b0), "r"(b1));
}

__global__ __launch_bounds__(256, 4)
void conv_mma_kernel(const float* __restrict__ rgb)
{
    extern __shared__ char sm[];
    const uint32_t* in32 = (const uint32_t*)sm;
    float* s_pool        = (float*)(sm + SMEM_POOL_OFF);

    int blk = blockIdx.x;
    int yp = blk % 28; int frame = blk / 28;
    int t = frame % TT; int b = frame / TT;
    int tid = threadIdx.x;
    int w = tid >> 5; int lane = tid & 31;
    int g = lane >> 2; int q = lane & 3;
    int wm = w & 3;    int nh = w >> 2;

    for (int i = tid; i < 576; i += 256) s_pool[i] = 0.f;

    // ---- input patch: 9 planes x 11 rows, 114 u32 (228 bf16) per row ----
    int rowbase = 8*yp - 3;
    for (int r = w; r < 99; r += 8) {
        int pIdx = r / 11, iy = r % 11;
        int tin = t + pIdx/3 - 1; int c = pIdx % 3;
        int grow = rowbase + iy;
        bool rv = (tin >= 0) && (tin < TT) && (grow >= 0) && (grow < HW);
        const float* src = rgb + (((size_t)(b*TT + tin)*3 + c)*HW + grow)*HW;
        uint32_t* dst = (uint32_t*)sm + (pIdx*11 + iy)*SIN_U32ROW;
        #pragma unroll
        for (int it = 0; it < 4; it++) {
            int x2 = lane + it*32;
            if (x2 < 114) {
                int c0 = 2*x2 - 3, c1 = c0 + 1;
                float v0 = (rv && c0 >= 0 && c0 < HW) ? src[c0] : 0.f;
                float v1 = (rv && c1 >= 0 && c1 < HW) ? src[c1] : 0.f;
                __nv_bfloat162 pk = __floats2bfloat162_rn(v0, v1);
                dst[x2] = *(uint32_t*)&pk;
            }
        }
    }
    __syncthreads();

    // per-thread A addressing (validated fragment mapping, R6)
    int x_lo = wm*16 + g;
    int x_hi = x_lo + 8; if (x_hi > 55) x_hi = 55;
    int blo = 2*x_lo + q;
    int bhi = 2*x_hi + q;

    float acc[2][4][4];
    #pragma unroll
    for (int y = 0; y < 2; y++)
        #pragma unroll
        for (int nt = 0; nt < 4; nt++)
            #pragma unroll
            for (int e = 0; e < 4; e++) acc[y][nt][e] = 0.f;

    const uint4* btab = g_wBv + nh*64 + lane;

    #pragma unroll
    for (int kt2 = 0; kt2 < 32; kt2++) {
        const int s0 = 2*kt2, s1 = s0 + 1;
        const int p0 = s0 / 7, ky0 = s0 - 7*p0;
        const int p1 = s1 / 7, ky1 = s1 - 7*p1;
        const int o0 = (p0*11 + ky0)*SIN_U32ROW;
        // s1==63 is the zero-weight pad slot: clamp to a VALID smem row
        const int o1 = (s1 == 63) ? o0 : (p1*11 + ky1)*SIN_U32ROW;

        uint4 B0 = __ldg(btab + kt2*128);
        uint4 B1 = __ldg(btab + kt2*128 + 32);

        uint32_t a0[4], a1[4];
        a0[0] = in32[o0 + blo];        a0[1] = in32[o0 + bhi];
        a0[2] = in32[o1 + blo];        a0[3] = in32[o1 + bhi];
        a1[0] = in32[o0 + 464 + blo];  a1[1] = in32[o0 + 464 + bhi];
        a1[2] = in32[o1 + 464 + blo];  a1[3] = in32[o1 + 464 + bhi];

        mma16816(acc[0][0], a0, B0.x, B0.y);  mma16816(acc[1][0], a1, B0.x, B0.y);
        mma16816(acc[0][1], a0, B0.z, B0.w);  mma16816(acc[1][1], a1, B0.z, B0.w);
        mma16816(acc[0][2], a0, B1.x, B1.y);  mma16816(acc[1][2], a1, B1.x, B1.y);
        mma16816(acc[0][3], a0, B1.z, B1.w);  mma16816(acc[1][3], a1, B1.z, B1.w);
    }

    // ---- epilogue: bias + exact GELU + pool bins (floor 18/19/19) ----
    // y=0 (row 2yp) and y=1 (row 2yp+1) share a row bin except yp==18,
    // so merge their contributions into ONE shared atomic in the common case.
    const float i18 = 1.f/18.f, i19 = 1.f/19.f;
    const int rowg0 = 2*yp, rowg1 = 2*yp + 1;
    const float rw0 = (rowg0 < 18) ? i18 : i19;
    const float rw1 = (rowg1 < 18) ? i18 : i19;
    const int roff0 = (rowg0 < 18) ? 0 : ((rowg0 < 37) ? 3 : 6);
    const int roff1 = (rowg1 < 18) ? 0 : ((rowg1 < 37) ? 3 : 6);
    const bool same = (roff0 == roff1);

    float biasv[8];
    #pragma unroll
    for (int nt = 0; nt < 4; nt++) {
        biasv[2*nt]   = __ldg(g_biasf + (nh*4 + nt)*8 + q*2);
        biasv[2*nt+1] = __ldg(g_biasf + (nh*4 + nt)*8 + q*2 + 1);
    }

    #pragma unroll
    for (int h = 0; h < 2; h++) {
        int x = wm*16 + g + h*8;
        if (x < 56) {
            int xbin = (x < 18) ? 0 : ((x < 37) ? 1 : 2);
            float cw = (x < 18) ? i18 : i19;
            #pragma unroll
            for (int nt = 0; nt < 4; nt++) {
                int ch0 = (nh*4 + nt)*8 + q*2;
                #pragma unroll
                for (int e = 0; e < 2; e++) {
                    float bv = biasv[2*nt + e];
                    float v0 = acc[0][nt][h*2 + e] + bv;
                    float v1 = acc[1][nt][h*2 + e] + bv;
                    float g0 = 0.5f*v0*(1.0f + erff(v0*0.70710678118654752f));
                    float g1 = 0.5f*v1*(1.0f + erff(v1*0.70710678118654752f));
                    float* base = &s_pool[(ch0 + e)*9 + xbin];
                    if (same) {
                        atomicAdd(base + roff0, (g0*rw0 + g1*rw1)*cw);
                    } else {
                        atomicAdd(base + roff0, g0*rw0*cw);
                        atomicAdd(base + roff1, g1*rw1*cw);
                    }
                }
            }
        }
    }
    __syncthreads();
    int base = frame*576;
    for (int i = tid; i < 576; i += 256) atomicAdd(&g_pooled[base + i], s_pool[i]);
}

// ================= Mamba chain — coalesced warp-per-row GEMVs =================
__global__ void proj_inproj_kernel(const float* __restrict__ proj_w,
                                   const float* __restrict__ proj_b,
                                   const float* __restrict__ in_w)
{
    __shared__ float s_p[576];
    __shared__ __align__(16) float s_x[128];
    int pos = blockIdx.x;
    int tid = threadIdx.x;           // 256
    int w = tid >> 5, lane = tid & 31;
    for (int i = tid; i < 576; i += 256) s_p[i] = g_pooled[pos*576 + i];
    __syncthreads();

    // phase 1: 128 rows of proj (K=576)
    #pragma unroll
    for (int rr = 0; rr < 16; rr++) {
        int row = w*16 + rr;
        const float* wr = proj_w + row*576;
        float a = 0.f;
        #pragma unroll
        for (int k = lane; k < 576; k += 32) a = fmaf(__ldg(wr + k), s_p[k], a);
        #pragma unroll
        for (int o = 16; o > 0; o >>= 1) a += __shfl_xor_sync(0xffffffffu, a, o);
        if (lane == 0) s_x[row] = a + __ldg(proj_b + row);
    }
    __syncthreads();

    // phase 2: 512 rows of in_proj (K=128 = exactly 1 float4 per lane)
    #pragma unroll
    for (int rr = 0; rr < 64; rr++) {
        int row = w*64 + rr;
        float4 wv = __ldg((const float4*)(in_w + row*128) + lane);
        float4 xv = *((const float4*)s_x + lane);
        float a = wv.x*xv.x + wv.y*xv.y + wv.z*xv.z + wv.w*xv.w;
        #pragma unroll
        for (int o = 16; o > 0; o >>= 1) a += __shfl_xor_sync(0xffffffffu, a, o);
        if (lane == 0) {
            if (row < 256) g_xm[pos*256 + row] = a;
            else           g_res[pos*256 + (row - 256)] = a;
        }
    }
}

__global__ void conv1d_xproj_kernel(const float* __restrict__ cw,
                                    const float* __restrict__ cb,
                                    const float* __restrict__ xw,
                                    const float* __restrict__ dtw,
                                    const float* __restrict__ dtb)
{
    __shared__ __align__(16) float s_u[256];
    __shared__ float s_xd[40];
    int pos = blockIdx.x; int b = pos / TT; int l = pos % TT;
    int d = threadIdx.x;             // 256
    int w = d >> 5, lane = d & 31;

    float xc = cb[d];
    #pragma unroll
    for (int k = 0; k < 4; k++) {
        int li = l - 3 + k;
        if (li >= 0) xc = fmaf(g_xm[(b*TT + li)*256 + d], cw[d*4 + k], xc);
    }
    float u = xc / (1.f + expf(-xc));
    s_u[d] = u;
    g_u[pos*256 + d] = u;
    __syncthreads();

    // x_proj: 40 rows (K=256 = 2 float4 per lane)
    #pragma unroll
    for (int rr = 0; rr < 5; rr++) {
        int row = w*5 + rr;
        float4 w0 = __ldg((const float4*)(xw + row*256) + lane);
        float4 w1 = __ldg((const float4*)(xw + row*256) + 32 + lane);
        float4 x0 = *((const float4*)s_u + lane);
        float4 x1 = *((const float4*)s_u + 32 + lane);
        float a = w0.x*x0.x + w0.y*x0.y + w0.z*x0.z + w0.w*x0.w
                + w1.x*x1.x + w1.y*x1.y + w1.z*x1.z + w1.w*x1.w;
        #pragma unroll
        for (int o = 16; o > 0; o >>= 1) a += __shfl_xor_sync(0xffffffffu, a, o);
        if (lane == 0) s_xd[row] = a;
    }
    __syncthreads();

    float dr = dtb[d];
    #pragma unroll
    for (int k = 0; k < 8; k++) dr = fmaf(dtw[d*8 + k], s_xd[k], dr);
    float delta = (dr > 20.f) ? dr : log1pf(expf(dr));
    g_delta[pos*256 + d] = delta;
    if (d < 32) g_BC[pos*32 + d] = s_xd[8 + d];
}

__global__ void scan_kernel(const float* __restrict__ A_log,
                            const float* __restrict__ Dp)
{
    int b = blockIdx.x >> 3;
    int d = ((blockIdx.x & 7) << 5) + threadIdx.x;
    float A[16], h[16];
    #pragma unroll
    for (int n = 0; n < 16; n++) { A[n] = -expf(A_log[d*16 + n]); h[n] = 0.f; }
    float Dd = Dp[d];

    for (int l = 0; l < TT; l++) {
        int pos = b*TT + l;
        float delta = g_delta[pos*256 + d];
        float u     = g_u[pos*256 + d];
        float res   = g_res[pos*256 + d];
        const float4* BC4 = (const float4*)(g_BC + pos*32);
        float4 Bv[4], Cv[4];
        #pragma unroll
        for (int i = 0; i < 4; i++) Bv[i] = __ldg(BC4 + i);
        #pragma unroll
        for (int i = 0; i < 4; i++) Cv[i] = __ldg(BC4 + 4 + i);
        float du = delta * u;
        float y = 0.f;
        const float* Bf = (const float*)Bv;
        const float* Cf = (const float*)Cv;
        #pragma unroll
        for (int n = 0; n < 16; n++) {
            float dA = expf(delta * A[n]);
            h[n] = fmaf(dA, h[n], du * Bf[n]);
            y = fmaf(h[n], Cf[n], y);
        }
        y = fmaf(u, Dd, y);
        y *= res / (1.f + expf(-res));
        g_y[pos*256 + d] = y;
    }
}

__global__ void outproj_kernel(const float* __restrict__ ow,
                               float* __restrict__ out)
{
    __shared__ __align__(16) float s_y[256];
    int pos = blockIdx.x;
    int tid = threadIdx.x;           // 256
    int w = tid >> 5, lane = tid & 31;
    s_y[tid] = g_y[pos*256 + tid];
    __syncthreads();
    // 128 rows (K=256 = 2 float4 per lane)
    #pragma unroll
    for (int rr = 0; rr < 16; rr++) {
        int row = w*16 + rr;
        float4 w0 = __ldg((const float4*)(ow + row*256) + lane);
        float4 w1 = __ldg((const float4*)(ow + row*256) + 32 + lane);
        float4 y0 = *((const float4*)s_y + lane);
        float4 y1 = *((const float4*)s_y + 32 + lane);
        float a = w0.x*y0.x + w0.y*y0.y + w0.z*y0.z + w0.w*y0.w
                + w1.x*y1.x + w1.y*y1.y + w1.z*y1.z + w1.w*y1.w;
        #pragma unroll
        for (int o = 16; o > 0; o >>= 1) a += __shfl_xor_sync(0xffffffffu, a, o);
        if (lane == 0) out[pos*128 + row] = a;
    }
}

// ============================================================
extern "C" void kernel_launch(void* const* d_in, const int* in_sizes, int n_in,
                              void* d_out, int out_size)
{
    (void)in_sizes; (void)n_in; (void)out_size;
    const float* rgb     = (const float*)d_in[0];
    const float* conv_w  = (const float*)d_in[1];
    const float* conv_b  = (const float*)d_in[2];
    const float* bn_g    = (const float*)d_in[3];
    const float* bn_b    = (const float*)d_in[4];
    const float* bn_m    = (const float*)d_in[5];
    const float* bn_v    = (const float*)d_in[6];
    const float* proj_w  = (const float*)d_in[7];
    const float* proj_b  = (const float*)d_in[8];
    const float* m_in_w  = (const float*)d_in[9];
    const float* m_cw    = (const float*)d_in[10];
    const float* m_cb    = (const float*)d_in[11];
    const float* m_xw    = (const float*)d_in[12];
    const float* m_dtw   = (const float*)d_in[13];
    const float* m_dtb   = (const float*)d_in[14];
    const float* m_Alog  = (const float*)d_in[15];
    const float* m_D     = (const float*)d_in[16];
    const float* m_ow    = (const float*)d_in[17];
    float* out = (float*)d_out;

    cudaFuncSetAttribute(conv_mma_kernel,
                         cudaFuncAttributeMaxDynamicSharedMemorySize, CONV_SMEM);

    prep_kernel<<<(FR*576 + 255)/256, 256>>>(conv_w, conv_b, bn_g, bn_b, bn_m, bn_v);

    conv_mma_kernel<<<FR*28, 256, CONV_SMEM>>>(rgb);

    proj_inproj_kernel<<<FR, 256>>>(proj_w, proj_b, m_in_w);
    conv1d_xproj_kernel<<<FR, 256>>>(m_cw, m_cb, m_xw, m_dtw, m_dtb);
    scan_kernel<<<32, 32>>>(m_Alog, m_D);
    outproj_kernel<<<FR, 256>>>(m_ow, out);
}

// round 15
// speedup vs baseline: 1.8961x; 1.0142x over previous
#include <cuda_runtime.h>
#include <cuda_bf16.h>
#include <math.h>
#include <stdint.h>

#define BB 4
#define TT 90
#define FR (BB*TT)          // 360 frames
#define HW 224
#define DIN 256

// ---- scratch (device globals; no allocation) ----
__device__ __align__(16) uint4 g_wBv[32*4*32];     // B frags: [kt2][j][lane], 64KB
__device__ float g_biasf[64];
__device__ __align__(16) float g_negA[256*16];     // -exp(A_log)
__device__ float g_pooled[FR*576];
__device__ float g_xm[FR*DIN];
__device__ float g_res[FR*DIN];
__device__ float g_u[FR*DIN];
__device__ float g_delta[FR*DIN];
__device__ __align__(16) float g_BC[FR*32];
__device__ float g_y[FR*DIN];

// ================= one-time prep =================
__global__ void wfold_kernel(const float* __restrict__ conv_w,
                             const float* __restrict__ conv_b,
                             const float* __restrict__ gma,
                             const float* __restrict__ bta,
                             const float* __restrict__ mean,
                             const float* __restrict__ var,
                             const float* __restrict__ A_log)
{
    int idx = blockIdx.x * 256 + threadIdx.x;
    if (idx < 64) {
        float inv = gma[idx] * rsqrtf(var[idx] + 1e-5f);
        g_biasf[idx] = (conv_b[idx] - mean[idx]) * inv + bta[idx];
    }
    if (idx < 4096) g_negA[idx] = -expf(A_log[idx]);
    if (idx >= 32*4*32) return;
    int kt2  = idx >> 7;
    int j    = (idx >> 5) & 3;
    int lane = idx & 31;
    uint32_t comp[4];
    #pragma unroll
    for (int c = 0; c < 4; c++) {
        int nt = 2*j + (c >> 1); int h = c & 1;
        int n = nt*8 + (lane >> 2);
        int kbase = kt2*16 + h*8 + (lane & 3)*2;
        float inv = gma[n] * rsqrtf(var[n] + 1e-5f);
        float v[2];
        #pragma unroll
        for (int e = 0; e < 2; e++) {
            int k = kbase + e;
            int s = k >> 3, kx = k & 7;
            float val = 0.f;
            if (s < 63 && kx < 7) {
                int p = s / 7, ky = s % 7;
                int kt = p / 3, cc = p % 3;
                val = conv_w[(n*3 + cc)*147 + kt*49 + ky*7 + kx] * inv;
            }
            v[e] = val;
        }
        __nv_bfloat162 pk = __floats2bfloat162_rn(v[0], v[1]);
        comp[c] = *(uint32_t*)&pk;
    }
    g_wBv[idx] = make_uint4(comp[0], comp[1], comp[2], comp[3]);
}

__global__ void zero_pooled_kernel(int off) {
    int i = off + blockIdx.x * 256 + threadIdx.x;
    if (i < FR*576) g_pooled[i] = 0.f;
}

// ================= conv via mma.sync (HMMA) — R10 core =================
#define SIN_U32ROW 116
#define SMEM_POOL_OFF 45936
#define CONV_SMEM (SMEM_POOL_OFF + 576*4)   // 48,240 B -> 4 CTAs/SM

__device__ __forceinline__ void mma16816(float* c, const uint32_t* a,
                                         uint32_t b0, uint32_t b1) {
    asm volatile(
        "mma.sync.aligned.m16n8k16.row.col.f32.bf16.bf16.f32 "
        "{%0,%1,%2,%3}, {%4,%5,%6,%7}, {%8,%9}, {%0,%1,%2,%3};"
        : "+f"(c[0]), "+f"(c[1]), "+f"(c[2]), "+f"(c[3])
        : "r"(a[0]), "r"(a[1]), "r"(a[2]), "r"(a[3]), "r"(b0), "r"(b1));
}

__device__ __forceinline__ float gelu_exact(float v) {
    return 0.5f * v * (1.0f + erff(v * 0.70710678118654752f));
}

__global__ __launch_bounds__(256, 4)
void conv_mma_kernel(const float* __restrict__ rgb)
{
    extern __shared__ char sm[];
    const uint32_t* in32 = (const uint32_t*)sm;
    float* s_pool        = (float*)(sm + SMEM_POOL_OFF);

    int blk = blockIdx.x;
    int yp = blk % 28; int frame = blk / 28;
    int t = frame % TT; int b = frame / TT;
    int tid = threadIdx.x;
    int w = tid >> 5; int lane = tid & 31;
    int g = lane >> 2; int q = lane & 3;
    int wm = w & 3;    int nh = w >> 2;

    for (int i = tid; i < 576; i += 256) s_pool[i] = 0.f;

    // ---- input patch: 9 planes x 11 rows, 114 u32 (228 bf16) per row ----
    int rowbase = 8*yp - 3;
    for (int r = w; r < 99; r += 8) {
        int pIdx = r / 11, iy = r % 11;
        int tin = t + pIdx/3 - 1; int c = pIdx % 3;
        int grow = rowbase + iy;
        bool rv = (tin >= 0) && (tin < TT) && (grow >= 0) && (grow < HW);
        const float* src = rgb + (((size_t)(b*TT + tin)*3 + c)*HW + grow)*HW;
        uint32_t* dst = (uint32_t*)sm + (pIdx*11 + iy)*SIN_U32ROW;
        #pragma unroll
        for (int it = 0; it < 4; it++) {
            int x2 = lane + it*32;
            if (x2 < 114) {
                int c0 = 2*x2 - 3, c1 = c0 + 1;
                float v0 = (rv && c0 >= 0 && c0 < HW) ? src[c0] : 0.f;
                float v1 = (rv && c1 >= 0 && c1 < HW) ? src[c1] : 0.f;
                __nv_bfloat162 pk = __floats2bfloat162_rn(v0, v1);
                dst[x2] = *(uint32_t*)&pk;
            }
        }
    }
    __syncthreads();

    // per-thread A addressing (validated fragment mapping, R6)
    int x_lo = wm*16 + g;
    int x_hi = x_lo + 8; if (x_hi > 55) x_hi = 55;
    int blo = 2*x_lo + q;
    int bhi = 2*x_hi + q;

    float acc[2][4][4];
    #pragma unroll
    for (int y = 0; y < 2; y++)
        #pragma unroll
        for (int nt = 0; nt < 4; nt++)
            #pragma unroll
            for (int e = 0; e < 4; e++) acc[y][nt][e] = 0.f;

    const uint4* btab = g_wBv + nh*64 + lane;

    #pragma unroll
    for (int kt2 = 0; kt2 < 32; kt2++) {
        const int s0 = 2*kt2, s1 = s0 + 1;
        const int p0 = s0 / 7, ky0 = s0 - 7*p0;
        const int p1 = s1 / 7, ky1 = s1 - 7*p1;
        const int o0 = (p0*11 + ky0)*SIN_U32ROW;
        // s1==63 is the zero-weight pad slot: clamp to a VALID smem row
        const int o1 = (s1 == 63) ? o0 : (p1*11 + ky1)*SIN_U32ROW;

        uint4 B0 = __ldg(btab + kt2*128);
        uint4 B1 = __ldg(btab + kt2*128 + 32);

        uint32_t a0[4], a1[4];
        a0[0] = in32[o0 + blo];        a0[1] = in32[o0 + bhi];
        a0[2] = in32[o1 + blo];        a0[3] = in32[o1 + bhi];
        a1[0] = in32[o0 + 464 + blo];  a1[1] = in32[o0 + 464 + bhi];
        a1[2] = in32[o1 + 464 + blo];  a1[3] = in32[o1 + 464 + bhi];

        mma16816(acc[0][0], a0, B0.x, B0.y);  mma16816(acc[1][0], a1, B0.x, B0.y);
        mma16816(acc[0][1], a0, B0.z, B0.w);  mma16816(acc[1][1], a1, B0.z, B0.w);
        mma16816(acc[0][2], a0, B1.x, B1.y);  mma16816(acc[1][2], a1, B1.x, B1.y);
        mma16816(acc[0][3], a0, B1.z, B1.w);  mma16816(acc[1][3], a1, B1.z, B1.w);
    }

    // ---- epilogue: bias + exact GELU + pool bins (floor 18/19/19) ----
    // y-merge (rows 2yp/2yp+1 share row-bin except yp==18) AND x-merge
    // (pixels x0 and x0+8 often share col-bin) to minimize shared atomics.
    const float i18 = 1.f/18.f, i19 = 1.f/19.f;
    const int rowg0 = 2*yp, rowg1 = 2*yp + 1;
    const float rw0 = (rowg0 < 18) ? i18 : i19;
    const float rw1 = (rowg1 < 18) ? i18 : i19;
    const int roff0 = (rowg0 < 18) ? 0 : ((rowg0 < 37) ? 3 : 6);
    const int roff1 = (rowg1 < 18) ? 0 : ((rowg1 < 37) ? 3 : 6);
    const bool ymerge = (roff0 == roff1);

    const int x0 = wm*16 + g;            // always < 56
    const int x1 = x0 + 8;
    const bool v1 = (x1 < 56);           // warp-uniform false for wm==3
    const int xb0 = (x0 < 18) ? 0 : ((x0 < 37) ? 1 : 2);
    const int xb1 = (x1 < 18) ? 0 : ((x1 < 37) ? 1 : 2);
    const float cw0 = (x0 < 18) ? i18 : i19;
    const float cw1 = (x1 < 18) ? i18 : i19;
    const bool xmerge = v1 && (xb0 == xb1);

    #pragma unroll
    for (int nt = 0; nt < 4; nt++) {
        int ch0 = (nh*4 + nt)*8 + q*2;
        #pragma unroll
        for (int e = 0; e < 2; e++) {
            float bv = __ldg(g_biasf + ch0 + e);
            float g00 = gelu_exact(acc[0][nt][e] + bv);       // y0,h0
            float g10 = gelu_exact(acc[1][nt][e] + bv);       // y1,h0
            float* base = &s_pool[(ch0 + e)*9];
            if (v1) {
                float g01 = gelu_exact(acc[0][nt][2 + e] + bv);   // y0,h1
                float g11 = gelu_exact(acc[1][nt][2 + e] + bv);   // y1,h1
                if (ymerge) {
                    if (xmerge) {
                        atomicAdd(base + roff0 + xb0,
                                  ((g00 + g01)*rw0 + (g10 + g11)*rw1)*cw0);
                    } else {
                        atomicAdd(base + roff0 + xb0, (g00*rw0 + g10*rw1)*cw0);
                        atomicAdd(base + roff0 + xb1, (g01*rw0 + g11*rw1)*cw1);
                    }
                } else {
                    atomicAdd(base + roff0 + xb0, g00*rw0*cw0);
                    atomicAdd(base + roff1 + xb0, g10*rw1*cw0);
                    atomicAdd(base + roff0 + xb1, g01*rw0*cw1);
                    atomicAdd(base + roff1 + xb1, g11*rw1*cw1);
                }
            } else {
                if (ymerge) {
                    atomicAdd(base + roff0 + xb0, (g00*rw0 + g10*rw1)*cw0);
                } else {
                    atomicAdd(base + roff0 + xb0, g00*rw0*cw0);
                    atomicAdd(base + roff1 + xb0, g10*rw1*cw0);
                }
            }
        }
    }
    __syncthreads();
    int base = frame*576;
    for (int i = tid; i < 576; i += 256) atomicAdd(&g_pooled[base + i], s_pool[i]);
}

// ================= Mamba chain — coalesced warp-per-row GEMVs =================
__global__ void proj_inproj_kernel(const float* __restrict__ proj_w,
                                   const float* __restrict__ proj_b,
                                   const float* __restrict__ in_w)
{
    __shared__ __align__(16) float s_p[576];
    __shared__ __align__(16) float s_x[128];
    int pos = blockIdx.x;
    int tid = threadIdx.x;           // 256
    int w = tid >> 5, lane = tid & 31;
    for (int i = tid; i < 576; i += 256) s_p[i] = g_pooled[pos*576 + i];
    __syncthreads();

    // phase 1: 128 rows of proj (K=576 = 144 float4: 4 full lane-strides + 16)
    const float4* p4 = (const float4*)s_p;
    #pragma unroll
    for (int rr = 0; rr < 16; rr++) {
        int row = w*16 + rr;
        const float4* w4 = (const float4*)(proj_w + row*576);
        float a = 0.f;
        #pragma unroll
        for (int i = 0; i < 4; i++) {
            float4 wv = __ldg(w4 + lane + 32*i);
            float4 xv = p4[lane + 32*i];
            a += wv.x*xv.x + wv.y*xv.y + wv.z*xv.z + wv.w*xv.w;
        }
        if (lane < 16) {
            float4 wv = __ldg(w4 + 128 + lane);
            float4 xv = p4[128 + lane];
            a += wv.x*xv.x + wv.y*xv.y + wv.z*xv.z + wv.w*xv.w;
        }
        #pragma unroll
        for (int o = 16; o > 0; o >>= 1) a += __shfl_xor_sync(0xffffffffu, a, o);
        if (lane == 0) s_x[row] = a + __ldg(proj_b + row);
    }
    __syncthreads();

    // phase 2: 512 rows of in_proj (K=128 = exactly 1 float4 per lane)
    #pragma unroll
    for (int rr = 0; rr < 64; rr++) {
        int row = w*64 + rr;
        float4 wv = __ldg((const float4*)(in_w + row*128) + lane);
        float4 xv = *((const float4*)s_x + lane);
        float a = wv.x*xv.x + wv.y*xv.y + wv.z*xv.z + wv.w*xv.w;
        #pragma unroll
        for (int o = 16; o > 0; o >>= 1) a += __shfl_xor_sync(0xffffffffu, a, o);
        if (lane == 0) {
            if (row < 256) g_xm[pos*256 + row] = a;
            else           g_res[pos*256 + (row - 256)] = a;
        }
    }
}

__global__ void conv1d_xproj_kernel(const float* __restrict__ cw,
                                    const float* __restrict__ cb,
                                    const float* __restrict__ xw,
                                    const float* __restrict__ dtw,
                                    const float* __restrict__ dtb)
{
    __shared__ __align__(16) float s_u[256];
    __shared__ float s_xd[40];
    int pos = blockIdx.x; int b = pos / TT; int l = pos % TT;
    int d = threadIdx.x;             // 256
    int w = d >> 5, lane = d & 31;

    float xc = cb[d];
    #pragma unroll
    for (int k = 0; k < 4; k++) {
        int li = l - 3 + k;
        if (li >= 0) xc = fmaf(g_xm[(b*TT + li)*256 + d], cw[d*4 + k], xc);
    }
    float u = xc / (1.f + expf(-xc));
    s_u[d] = u;
    g_u[pos*256 + d] = u;
    __syncthreads();

    // x_proj: 40 rows (K=256 = 2 float4 per lane)
    #pragma unroll
    for (int rr = 0; rr < 5; rr++) {
        int row = w*5 + rr;
        float4 w0 = __ldg((const float4*)(xw + row*256) + lane);
        float4 w1 = __ldg((const float4*)(xw + row*256) + 32 + lane);
        float4 x0 = *((const float4*)s_u + lane);
        float4 x1 = *((const float4*)s_u + 32 + lane);
        float a = w0.x*x0.x + w0.y*x0.y + w0.z*x0.z + w0.w*x0.w
                + w1.x*x1.x + w1.y*x1.y + w1.z*x1.z + w1.w*x1.w;
        #pragma unroll
        for (int o = 16; o > 0; o >>= 1) a += __shfl_xor_sync(0xffffffffu, a, o);
        if (lane == 0) s_xd[row] = a;
    }
    __syncthreads();

    float dr = dtb[d];
    #pragma unroll
    for (int k = 0; k < 8; k++) dr = fmaf(dtw[d*8 + k], s_xd[k], dr);
    float delta = (dr > 20.f) ? dr : log1pf(expf(dr));
    g_delta[pos*256 + d] = delta;
    if (d < 32) g_BC[pos*32 + d] = s_xd[8 + d];
}

__global__ void scan_kernel(const float* __restrict__ Dp)
{
    int b = blockIdx.x >> 3;
    int d = ((blockIdx.x & 7) << 5) + threadIdx.x;
    float A[16], h[16];
    {
        const float4* A4 = (const float4*)(g_negA + d*16);
        #pragma unroll
        for (int i = 0; i < 4; i++) {
            float4 v = __ldg(A4 + i);
            A[4*i] = v.x; A[4*i+1] = v.y; A[4*i+2] = v.z; A[4*i+3] = v.w;
        }
    }
    #pragma unroll
    for (int n = 0; n < 16; n++) h[n] = 0.f;
    float Dd = Dp[d];

    for (int l = 0; l < TT; l++) {
        int pos = b*TT + l;
        float delta = g_delta[pos*256 + d];
        float u     = g_u[pos*256 + d];
        float res   = g_res[pos*256 + d];
        const float4* BC4 = (const float4*)(g_BC + pos*32);
        float4 Bv[4], Cv[4];
        #pragma unroll
        for (int i = 0; i < 4; i++) Bv[i] = __ldg(BC4 + i);
        #pragma unroll
        for (int i = 0; i < 4; i++) Cv[i] = __ldg(BC4 + 4 + i);
        float du = delta * u;
        float y = 0.f;
        const float* Bf = (const float*)Bv;
        const float* Cf = (const float*)Cv;
        #pragma unroll
        for (int n = 0; n < 16; n++) {
            float dA = expf(delta * A[n]);
            h[n] = fmaf(dA, h[n], du * Bf[n]);
            y = fmaf(h[n], Cf[n], y);
        }
        y = fmaf(u, Dd, y);
        y *= res / (1.f + expf(-res));
        g_y[pos*256 + d] = y;
    }
}

__global__ void outproj_kernel(const float* __restrict__ ow,
                               float* __restrict__ out)
{
    __shared__ __align__(16) float s_y[256];
    int pos = blockIdx.x;
    int tid = threadIdx.x;           // 256
    int w = tid >> 5, lane = tid & 31;
    s_y[tid] = g_y[pos*256 + tid];
    __syncthreads();
    #pragma unroll
    for (int rr = 0; rr < 16; rr++) {
        int row = w*16 + rr;
        float4 w0 = __ldg((const float4*)(ow + row*256) + lane);
        float4 w1 = __ldg((const float4*)(ow + row*256) + 32 + lane);
        float4 y0 = *((const float4*)s_y + lane);
        float4 y1 = *((const float4*)s_y + 32 + lane);
        float a = w0.x*y0.x + w0.y*y0.y + w0.z*y0.z + w0.w*y0.w
                + w1.x*y1.x + w1.y*y1.y + w1.z*y1.z + w1.w*y1.w;
        #pragma unroll
        for (int o = 16; o > 0; o >>= 1) a += __shfl_xor_sync(0xffffffffu, a, o);
        if (lane == 0) out[pos*128 + row] = a;
    }
}

// ============================================================
extern "C" void kernel_launch(void* const* d_in, const int* in_sizes, int n_in,
                              void* d_out, int out_size)
{
    (void)in_sizes; (void)n_in; (void)out_size;
    const float* rgb     = (const float*)d_in[0];
    const float* conv_w  = (const float*)d_in[1];
    const float* conv_b  = (const float*)d_in[2];
    const float* bn_g    = (const float*)d_in[3];
    const float* bn_b    = (const float*)d_in[4];
    const float* bn_m    = (const float*)d_in[5];
    const float* bn_v    = (const float*)d_in[6];
    const float* proj_w  = (const float*)d_in[7];
    const float* proj_b  = (const float*)d_in[8];
    const float* m_in_w  = (const float*)d_in[9];
    const float* m_cw    = (const float*)d_in[10];
    const float* m_cb    = (const float*)d_in[11];
    const float* m_xw    = (const float*)d_in[12];
    const float* m_dtw   = (const float*)d_in[13];
    const float* m_dtb   = (const float*)d_in[14];
    const float* m_Alog  = (const float*)d_in[15];
    const float* m_D     = (const float*)d_in[16];
    const float* m_ow    = (const float*)d_in[17];
    float* out = (float*)d_out;

    cudaFuncSetAttribute(conv_mma_kernel,
                         cudaFuncAttributeMaxDynamicSharedMemorySize, CONV_SMEM);

    // wfold + 2 zeros position conv at ncu launch index 5
    wfold_kernel<<<(32*4*32 + 255)/256, 256>>>(conv_w, conv_b, bn_g, bn_b,
                                               bn_m, bn_v, m_Alog);
    const int H = (FR*576) / 2;
    zero_pooled_kernel<<<(H + 255)/256, 256>>>(0);
    zero_pooled_kernel<<<(H + 255)/256, 256>>>(H);

    conv_mma_kernel<<<FR*28, 256, CONV_SMEM>>>(rgb);

    proj_inproj_kernel<<<FR, 256>>>(proj_w, proj_b, m_in_w);
    conv1d_xproj_kernel<<<FR, 256>>>(m_cw, m_cb, m_xw, m_dtw, m_dtb);
    scan_kernel<<<32, 32>>>(m_D);
    outproj_kernel<<<FR, 256>>>(m_ow, out);
}